// round 7
// baseline (speedup 1.0000x reference)
#include <cuda_runtime.h>
#include <cstdint>

// Correlation D=4, S1=S2=1 ; x1,x2:(4,128,256,256) f32 ; out:(4,81,256,256) f32
//
// Block (8,8,9)=576 threads, tile 8x32, PPT=4 scalar FFMA, 36 acc/thread.
// CB=16 channels/stage (8 stages), 3-buffer cp.async ring (192KB smem),
// fully hoisted loader (6 fixed float4 slots + 1 conditional), 1 barrier/stage.

#define Himg 256
#define Wimg 256
#define Cimg 128
#define TH 8
#define TW 32
#define CB 16
#define NSTAGE (Cimg/CB)      // 8
#define S2F 48
#define X1F (CB*TH*TW)        // 4096 floats (x1 part per buffer)
#define X2F (CB*16*S2F)       // 12288 floats (x2 part per buffer)
#define BUFF (X1F + X2F)      // 16384 floats
#define BUFB (BUFF*4)         // 65536 B
#define SMEM_BYTES (3*BUFB)   // 196608 B
#define CSTRIDE (CB*Himg*Wimg)
#define NTHREADS 576
#define NTASKS (CB*224)       // 3584 float4 tasks per stage

__device__ __forceinline__ void cp_async16(uint32_t dst, const float* src, int sz) {
    asm volatile("cp.async.cg.shared.global [%0], [%1], 16, %2;\n"
                 :: "r"(dst), "l"(src), "r"(sz) : "memory");
}
__device__ __forceinline__ void cp_commit() {
    asm volatile("cp.async.commit_group;\n" ::: "memory");
}

__global__ void __launch_bounds__(NTHREADS, 1)
corr_kernel(const float* __restrict__ x1, const float* __restrict__ x2,
            float* __restrict__ out) {
    const int wg = threadIdx.x;   // 0..7
    const int ty = threadIdx.y;   // 0..7
    const int ky = threadIdx.z;   // 0..8
    const int tid = wg + (ty << 3) + (ky << 6);

    const int w0 = blockIdx.x * TW;
    const int h0 = blockIdx.y * TH;
    const int n  = blockIdx.z;

    extern __shared__ float sm[];
    const uint32_t smem_u = (uint32_t)__cvta_generic_to_shared(sm);

    const float* x1n = x1 + (size_t)n * Cimg * Himg * Wimg;
    const float* x2n = x2 + (size_t)n * Cimg * Himg * Wimg;

    // ---------- loader: fixed per-thread slots, computed once ----------
    // task t < 3584: c = t/224, r = t%224
    //   r <  64 : x1 tile  row r/8,  chunk r%8
    //   r >= 64 : x2 halo  row (r-64)/10, chunk (r-64)%10 (zfill at borders)
    const float* lsrc[7];
    uint32_t     ldst[7];
    int          lsz[7];
    #pragma unroll
    for (int k = 0; k < 7; ++k) {
        const int t = tid + k * NTHREADS;
        if (t < NTASKS) {
            const int c = t / 224;
            const int r = t % 224;
            if (r < 64) {
                const int row = r >> 3, v = r & 7;
                lsrc[k] = x1n + ((size_t)(c * Himg + h0 + row)) * Wimg + w0 + v * 4;
                ldst[k] = smem_u + ((c * TH + row) * TW + v * 4) * 4;
                lsz[k]  = 16;
            } else {
                const int r2 = r - 64;
                const int row = r2 / 10, v = r2 % 10;
                const int hr = h0 - 4 + row;
                const int gw = w0 - 4 + v * 4;
                const bool ok = ((unsigned)hr < (unsigned)Himg) && (gw >= 0) && (gw <= Wimg - 4);
                lsrc[k] = x2n + ((size_t)(c * Himg + (ok ? hr : 0))) * Wimg + (ok ? gw : 0);
                ldst[k] = smem_u + (X1F + (c * 16 + row) * S2F + v * 4) * 4;
                lsz[k]  = ok ? 16 : 0;
            }
        } else {
            lsrc[k] = x1n; ldst[k] = smem_u; lsz[k] = -1;
        }
    }
    const bool has7 = (lsz[6] >= 0);   // only tid < 128

    auto load_stage = [&](int buf) {
        const uint32_t base = buf * BUFB;
        cp_async16(ldst[0] + base, lsrc[0], lsz[0]);
        cp_async16(ldst[1] + base, lsrc[1], lsz[1]);
        cp_async16(ldst[2] + base, lsrc[2], lsz[2]);
        cp_async16(ldst[3] + base, lsrc[3], lsz[3]);
        cp_async16(ldst[4] + base, lsrc[4], lsz[4]);
        cp_async16(ldst[5] + base, lsrc[5], lsz[5]);
        if (has7) cp_async16(ldst[6] + base, lsrc[6], lsz[6]);
        cp_commit();
        #pragma unroll
        for (int k = 0; k < 7; ++k) lsrc[k] += CSTRIDE;
    };

    // ---------- compute bases ----------
    const float* x1rb = sm + ty * TW + wg * 4;
    const float* x2rb = sm + X1F + (ty + ky) * S2F + wg * 4;

    float acc[36];
    #pragma unroll
    for (int i = 0; i < 36; ++i) acc[i] = 0.0f;

    auto compute_stage = [&](int buf) {
        const float* x1b = x1rb + buf * BUFF;
        const float* x2b = x2rb + buf * BUFF;
        #pragma unroll
        for (int c = 0; c < CB; ++c) {
            float4 a  = *reinterpret_cast<const float4*>(x1b + c * (TH * TW));
            float4 b0 = *reinterpret_cast<const float4*>(x2b + c * (16 * S2F));
            float4 b1 = *reinterpret_cast<const float4*>(x2b + c * (16 * S2F) + 4);
            float4 b2 = *reinterpret_cast<const float4*>(x2b + c * (16 * S2F) + 8);
            const float av[4] = {a.x, a.y, a.z, a.w};
            const float v[12] = {b0.x, b0.y, b0.z, b0.w,
                                 b1.x, b1.y, b1.z, b1.w,
                                 b2.x, b2.y, b2.z, b2.w};
            #pragma unroll
            for (int p = 0; p < 4; ++p)
                #pragma unroll
                for (int kx = 0; kx < 9; ++kx)
                    acc[p * 9 + kx] = fmaf(av[p], v[p + kx], acc[p * 9 + kx]);
        }
    };

    // ---------- 3-buffer ring, one barrier per stage ----------
    load_stage(0);
    load_stage(1);

    int bufl = 2;   // load target for stage s+2
    int bufc = 0;   // compute buffer for stage s
    #pragma unroll 1
    for (int s = 0; s < NSTAGE; ++s) {
        if (s < NSTAGE - 1) asm volatile("cp.async.wait_group 1;\n" ::: "memory");
        else                asm volatile("cp.async.wait_group 0;\n" ::: "memory");
        __syncthreads();   // buffer s ready; buffer bufl (computed at s-1) drained
        if (s < NSTAGE - 2) {
            load_stage(bufl);
            bufl = (bufl == 2) ? 0 : bufl + 1;
        }
        compute_stage(bufc);
        bufc = (bufc == 2) ? 0 : bufc + 1;
    }

    // ---------- epilogue ----------
    const float inv = 1.0f / (float)Cimg;
    float* op = out + ((size_t)(n * 81 + ky * 9) * (Himg * Wimg))
                    + (size_t)(h0 + ty) * Wimg + w0 + wg * 4;
    #pragma unroll
    for (int kx = 0; kx < 9; ++kx) {
        float4 r;
        r.x = acc[0 * 9 + kx] * inv;
        r.y = acc[1 * 9 + kx] * inv;
        r.z = acc[2 * 9 + kx] * inv;
        r.w = acc[3 * 9 + kx] * inv;
        *reinterpret_cast<float4*>(op + (size_t)kx * (Himg * Wimg)) = r;
    }
}

extern "C" void kernel_launch(void* const* d_in, const int* in_sizes, int n_in,
                              void* d_out, int out_size) {
    const float* x1 = (const float*)d_in[0];
    const float* x2 = (const float*)d_in[1];
    float* out = (float*)d_out;

    cudaFuncSetAttribute(corr_kernel, cudaFuncAttributeMaxDynamicSharedMemorySize,
                         SMEM_BYTES);

    dim3 block(8, 8, 9);                 // 576 threads
    dim3 grid(Wimg / TW, Himg / TH, 4);  // 1024 blocks
    corr_kernel<<<grid, block, SMEM_BYTES>>>(x1, x2, out);
}

// round 8
// speedup vs baseline: 1.0485x; 1.0485x over previous
#include <cuda_runtime.h>
#include <cstdint>

// Correlation D=4, S1=S2=1 ; x1,x2:(4,128,256,256) f32 ; out:(4,81,256,256) f32
//
// Persistent version of the R5 champion: grid=148 CTAs, each loops over
// tiles (8x32 pixels, all 81 displacements). The 3-buffer cp.async ring and
// stage counter run CONTINUOUSLY across tiles: during a tile's last two
// stages the loader is re-pointed at the next tile's first two stages, so
// there is no pipeline drain at tile boundaries (epilogue overlaps loads).
// Compute: block (8,8,9)=576 thr, PPT=4 scalar FFMA, 36 acc/thread, CB=8.

#define Himg 256
#define Wimg 256
#define Cimg 128
#define TH 8
#define TW 32
#define CB 8
#define NSTAGE 16
#define S2F 48
#define X1F (CB*TH*TW)        // 2048 floats (x1 part per buffer)
#define X2F (CB*16*S2F)       // 6144 floats (x2 part per buffer)
#define BUFF (X1F + X2F)      // 8192 floats
#define BUFB (BUFF*4)         // 32768 B
#define SMEM_BYTES (3*BUFB)   // 98304 B
#define CSTRIDE (CB*Himg*Wimg)
#define NTHREADS 576
#define NTASKS 1792
#define NTILES 1024
#define GRIDX 148

__device__ __forceinline__ void cp_async16(uint32_t dst, const float* src, int sz) {
    asm volatile("cp.async.cg.shared.global [%0], [%1], 16, %2;\n"
                 :: "r"(dst), "l"(src), "r"(sz) : "memory");
}
__device__ __forceinline__ void cp_commit() {
    asm volatile("cp.async.commit_group;\n" ::: "memory");
}

__global__ void __launch_bounds__(NTHREADS, 1)
corr_kernel(const float* __restrict__ x1, const float* __restrict__ x2,
            float* __restrict__ out) {
    const int wg = threadIdx.x;   // 0..7
    const int ty = threadIdx.y;   // 0..7
    const int ky = threadIdx.z;   // 0..8
    const int tid = wg + (ty << 3) + (ky << 6);

    extern __shared__ float sm[];
    const uint32_t smem_u = (uint32_t)__cvta_generic_to_shared(sm);

    // ---------- loader slot state (re-pointed once per tile) ----------
    const float* lsrc[4] = {x1, x1, x1, x1};
    uint32_t     ldst[4] = {smem_u, smem_u, smem_u, smem_u};
    int          lsz[4]  = {0, 0, 0, 0};
    const bool has4 = (tid < (NTASKS - 3 * NTHREADS));   // tid < 64

    auto make_slots = [&](int t_idx) {
        const int w0 = (t_idx & 7) * TW;
        const int h0 = ((t_idx >> 3) & 31) * TH;
        const int n  = t_idx >> 8;
        const float* x1n = x1 + (size_t)n * Cimg * Himg * Wimg;
        const float* x2n = x2 + (size_t)n * Cimg * Himg * Wimg;
        #pragma unroll
        for (int k = 0; k < 4; ++k) {
            const int t = tid + k * NTHREADS;
            if (t < NTASKS) {
                const int c = t / 224;
                const int r = t % 224;
                if (r < 64) {
                    const int row = r >> 3, v = r & 7;
                    lsrc[k] = x1n + ((size_t)(c * Himg + h0 + row)) * Wimg + w0 + v * 4;
                    ldst[k] = smem_u + ((c * TH + row) * TW + v * 4) * 4;
                    lsz[k]  = 16;
                } else {
                    const int r2 = r - 64;
                    const int row = r2 / 10, v = r2 % 10;
                    const int hr = h0 - 4 + row;
                    const int gw = w0 - 4 + v * 4;
                    const bool ok = ((unsigned)hr < (unsigned)Himg) && (gw >= 0) && (gw <= Wimg - 4);
                    lsrc[k] = x2n + ((size_t)(c * Himg + (ok ? hr : 0))) * Wimg + (ok ? gw : 0);
                    ldst[k] = smem_u + (X1F + (c * 16 + row) * S2F + v * 4) * 4;
                    lsz[k]  = ok ? 16 : 0;
                }
            }
        }
    };

    auto load_stage = [&](int buf) {
        const uint32_t base = buf * BUFB;
        cp_async16(ldst[0] + base, lsrc[0], lsz[0]);
        cp_async16(ldst[1] + base, lsrc[1], lsz[1]);
        cp_async16(ldst[2] + base, lsrc[2], lsz[2]);
        if (has4) cp_async16(ldst[3] + base, lsrc[3], lsz[3]);
        cp_commit();
        lsrc[0] += CSTRIDE; lsrc[1] += CSTRIDE; lsrc[2] += CSTRIDE; lsrc[3] += CSTRIDE;
    };

    // ---------- compute bases (tile-independent smem addresses) ----------
    const float* x1rb = sm + ty * TW + wg * 4;
    const float* x2rb = sm + X1F + (ty + ky) * S2F + wg * 4;

    float acc[36];
    #pragma unroll
    for (int i = 0; i < 36; ++i) acc[i] = 0.0f;

    auto compute_stage = [&](int buf) {
        const float* x1b = x1rb + buf * BUFF;
        const float* x2b = x2rb + buf * BUFF;
        #pragma unroll
        for (int c = 0; c < CB; ++c) {
            float4 a  = *reinterpret_cast<const float4*>(x1b + c * (TH * TW));
            float4 b0 = *reinterpret_cast<const float4*>(x2b + c * (16 * S2F));
            float4 b1 = *reinterpret_cast<const float4*>(x2b + c * (16 * S2F) + 4);
            float4 b2 = *reinterpret_cast<const float4*>(x2b + c * (16 * S2F) + 8);
            const float av[4] = {a.x, a.y, a.z, a.w};
            const float v[12] = {b0.x, b0.y, b0.z, b0.w,
                                 b1.x, b1.y, b1.z, b1.w,
                                 b2.x, b2.y, b2.z, b2.w};
            #pragma unroll
            for (int p = 0; p < 4; ++p)
                #pragma unroll
                for (int kx = 0; kx < 9; ++kx)
                    acc[p * 9 + kx] = fmaf(av[p], v[p + kx], acc[p * 9 + kx]);
        }
    };

    // ---------- persistent tile loop with seamless ring ----------
    make_slots(blockIdx.x);
    load_stage(0);       // tile0 stage 0
    load_stage(1);       // tile0 stage 1
    int bufl = 2;        // load target (stage s+2 of rolling counter)
    int bufc = 0;        // compute buffer

    #pragma unroll 1
    for (int tile = blockIdx.x; tile < NTILES; tile += GRIDX) {
        // stages 0..13: load this tile's stages 2..15
        #pragma unroll 1
        for (int s = 0; s < NSTAGE - 2; ++s) {
            asm volatile("cp.async.wait_group 1;\n" ::: "memory");
            __syncthreads();
            load_stage(bufl);
            bufl = (bufl == 2) ? 0 : bufl + 1;
            compute_stage(bufc);
            bufc = (bufc == 2) ? 0 : bufc + 1;
        }
        // re-point loader at next tile (clamped on the last tile)
        {
            int nxt = tile + GRIDX;
            make_slots(nxt < NTILES ? nxt : tile);
        }
        // stages 14,15: load next tile's stages 0,1
        #pragma unroll 1
        for (int s = 0; s < 2; ++s) {
            asm volatile("cp.async.wait_group 1;\n" ::: "memory");
            __syncthreads();
            load_stage(bufl);
            bufl = (bufl == 2) ? 0 : bufl + 1;
            compute_stage(bufc);
            bufc = (bufc == 2) ? 0 : bufc + 1;
        }

        // ---------- epilogue for this tile (overlaps next tile's loads) ----
        const int w0 = (tile & 7) * TW;
        const int h0 = ((tile >> 3) & 31) * TH;
        const int n  = tile >> 8;
        const float inv = 1.0f / (float)Cimg;
        float* op = out + ((size_t)(n * 81 + ky * 9) * (Himg * Wimg))
                        + (size_t)(h0 + ty) * Wimg + w0 + wg * 4;
        #pragma unroll
        for (int kx = 0; kx < 9; ++kx) {
            float4 r;
            r.x = acc[0 * 9 + kx] * inv;
            r.y = acc[1 * 9 + kx] * inv;
            r.z = acc[2 * 9 + kx] * inv;
            r.w = acc[3 * 9 + kx] * inv;
            *reinterpret_cast<float4*>(op + (size_t)kx * (Himg * Wimg)) = r;
        }
        #pragma unroll
        for (int i = 0; i < 36; ++i) acc[i] = 0.0f;
    }
}

extern "C" void kernel_launch(void* const* d_in, const int* in_sizes, int n_in,
                              void* d_out, int out_size) {
    const float* x1 = (const float*)d_in[0];
    const float* x2 = (const float*)d_in[1];
    float* out = (float*)d_out;

    cudaFuncSetAttribute(corr_kernel, cudaFuncAttributeMaxDynamicSharedMemorySize,
                         SMEM_BYTES);

    dim3 block(8, 8, 9);        // 576 threads
    dim3 grid(GRIDX, 1, 1);     // persistent: one CTA per SM
    corr_kernel<<<grid, block, SMEM_BYTES>>>(x1, x2, out);
}